// round 16
// baseline (speedup 1.0000x reference)
#include <cuda_runtime.h>
#include <cuda_fp16.h>
#include <cstdint>

#define NDIM 128
#define MAX_NODES 100000
#define APAD 136   // smem row stride in halves (128 + 8): conflict-free fragments

// Scratch: fp16 z table, fp16 x_source copy, dtype flag.
__device__ __half g_z_h[MAX_NODES * NDIM];    // 25.6 MB
__device__ __half g_xs_h[MAX_NODES * NDIM];   // 25.6 MB
__device__ int    g_idx_is64;

// ---------------------------------------------------------------------------
// Kernel 1 (fused, block-range partitioned):
//   blocks [0, n_gemm)          : tensor-core GEMM z = xt @ W^T
//   blocks [n_gemm, gridDim.x)  : grid-stride convert x_source -> fp16
//                                 (first convert block also detects idx dtype)
// GEMM: mma.sync.m16n8k16.row.col.f32.f16.f16.f32, A tile staged in dynamic
// shared via bulk coalesced float4 loads; 16 NAMED SCALAR accumulators
// (register arrays => lmem demotion => 128 MiB pool growth => violation).
// Dynamic smem: A[128][136] + W[128][136] fp16 = 68 KB (convert blocks just
// reserve it, unused).
// ---------------------------------------------------------------------------
__global__ void __launch_bounds__(256) gemm_conv_kernel(
    const float* __restrict__ xt,
    const float* __restrict__ W,
    const float* __restrict__ xs,  int n_elem4,
    const int*   __restrict__ eli_words, int nwords,
    int n_rows, int n_gemm_blocks) {
    extern __shared__ __half smem[];
    const int tid = threadIdx.x;

    // ---------------- convert / detect blocks ----------------
    if (blockIdx.x >= n_gemm_blocks) {
        const int cb     = blockIdx.x - n_gemm_blocks;
        const int n_conv = gridDim.x - n_gemm_blocks;

        if (cb == 0) {
            __shared__ int s_any_nonzero;
            if (tid == 0) s_any_nonzero = 0;
            __syncthreads();
            for (int i = 1 + 2 * tid; i < nwords; i += 2 * blockDim.x) {
                if (eli_words[i] != 0) { s_any_nonzero = 1; break; }
            }
            __syncthreads();
            if (tid == 0) g_idx_is64 = (s_any_nonzero == 0) ? 1 : 0;
        }

        const int stride = n_conv * 256;
        for (int i = cb * 256 + tid; i < n_elem4; i += stride) {
            float4 v = *(const float4*)(xs + (size_t)i * 4);
            *(__half2*)(g_xs_h + (size_t)i * 4)     = __floats2half2_rn(v.x, v.y);
            *(__half2*)(g_xs_h + (size_t)i * 4 + 2) = __floats2half2_rn(v.z, v.w);
        }
        return;
    }

    // ---------------- GEMM blocks ----------------
    __half* A_sh = smem;                 // [128][APAD]
    __half* W_sh = smem + NDIM * APAD;   // [128][APAD]
    const int block_base = blockIdx.x * 128;

    // stage W (fp32 -> fp16)
    for (int i = tid; i < NDIM * NDIM; i += 256) {
        int r = i >> 7;
        int c = i & (NDIM - 1);
        W_sh[r * APAD + c] = __float2half_rn(W[i]);
    }

    // stage A tile: 128 rows x 32 float4 = 4096 chunks, 16 per thread
#pragma unroll 4
    for (int i = tid; i < 128 * 32; i += 256) {
        int r  = i >> 5;
        int c4 = i & 31;
        int grow = block_base + r;
        if (grow >= n_rows) grow = n_rows - 1;   // clamp (stores guarded later)
        float4 v = *(const float4*)(xt + (size_t)grow * NDIM + c4 * 4);
        __half2 h0 = __floats2half2_rn(v.x, v.y);
        __half2 h1 = __floats2half2_rn(v.z, v.w);
        __half* p = A_sh + r * APAD + c4 * 4;
        *(__half2*)(p)     = h0;
        *(__half2*)(p + 2) = h1;
    }
    __syncthreads();

    const int warp = tid >> 5;
    const int lane = tid & 31;
    const int g = lane >> 2;        // 0..7
    const int t = lane & 3;         // 0..3
    const int row_base = block_base + warp * 16;
    if (row_base >= n_rows) return;

    const __half* Arow0 = A_sh + (warp * 16 + g)     * APAD + 2 * t;
    const __half* Arow1 = A_sh + (warp * 16 + g + 8) * APAD + 2 * t;
    const int row0 = row_base + g;
    const int row1 = row_base + g + 8;

#define LOAD_A(k0, a0, a1, a2, a3)                                   \
    unsigned int a0, a1, a2, a3;                                      \
    {                                                                 \
        a0 = *(const unsigned int*)(Arow0 + (k0));                    \
        a1 = *(const unsigned int*)(Arow1 + (k0));                    \
        a2 = *(const unsigned int*)(Arow0 + (k0) + 8);                \
        a3 = *(const unsigned int*)(Arow1 + (k0) + 8);                \
    }

#define MMA_STEP(k0, A0r, A1r, A2r, A3r, C0, C1, C2, C3, NROW)                    \
    {                                                                             \
        unsigned int b0 = *(const unsigned int*)(W_sh + ((NROW) + g) * APAD + (k0) + 2 * t);     \
        unsigned int b1 = *(const unsigned int*)(W_sh + ((NROW) + g) * APAD + (k0) + 2 * t + 8); \
        asm volatile(                                                             \
            "mma.sync.aligned.m16n8k16.row.col.f32.f16.f16.f32 "                  \
            "{%0,%1,%2,%3}, {%4,%5,%6,%7}, {%8,%9}, {%0,%1,%2,%3};"               \
            : "+f"(C0), "+f"(C1), "+f"(C2), "+f"(C3)                              \
            : "r"(A0r), "r"(A1r), "r"(A2r), "r"(A3r), "r"(b0), "r"(b1));          \
    }

#pragma unroll 1
    for (int ntg = 0; ntg < 4; ntg++) {
        const int n0 = ntg * 32;
        float c00 = 0.f, c01 = 0.f, c02 = 0.f, c03 = 0.f;
        float c10 = 0.f, c11 = 0.f, c12 = 0.f, c13 = 0.f;
        float c20 = 0.f, c21 = 0.f, c22 = 0.f, c23 = 0.f;
        float c30 = 0.f, c31 = 0.f, c32 = 0.f, c33 = 0.f;

#pragma unroll 1
        for (int k0 = 0; k0 < NDIM; k0 += 32) {
            LOAD_A(k0,      p0, p1, p2, p3)
            LOAD_A(k0 + 16, q0, q1, q2, q3)

            MMA_STEP(k0, p0, p1, p2, p3, c00, c01, c02, c03, n0)
            MMA_STEP(k0, p0, p1, p2, p3, c10, c11, c12, c13, n0 + 8)
            MMA_STEP(k0, p0, p1, p2, p3, c20, c21, c22, c23, n0 + 16)
            MMA_STEP(k0, p0, p1, p2, p3, c30, c31, c32, c33, n0 + 24)

            MMA_STEP(k0 + 16, q0, q1, q2, q3, c00, c01, c02, c03, n0)
            MMA_STEP(k0 + 16, q0, q1, q2, q3, c10, c11, c12, c13, n0 + 8)
            MMA_STEP(k0 + 16, q0, q1, q2, q3, c20, c21, c22, c23, n0 + 16)
            MMA_STEP(k0 + 16, q0, q1, q2, q3, c30, c31, c32, c33, n0 + 24)
        }

        const int colb = n0 + 2 * t;
        if (row0 < n_rows) {
            __half* zp = g_z_h + (size_t)row0 * NDIM;
            *(__half2*)(zp + colb)      = __floats2half2_rn(c00, c01);
            *(__half2*)(zp + colb + 8)  = __floats2half2_rn(c10, c11);
            *(__half2*)(zp + colb + 16) = __floats2half2_rn(c20, c21);
            *(__half2*)(zp + colb + 24) = __floats2half2_rn(c30, c31);
        }
        if (row1 < n_rows) {
            __half* zp = g_z_h + (size_t)row1 * NDIM;
            *(__half2*)(zp + colb)      = __floats2half2_rn(c02, c03);
            *(__half2*)(zp + colb + 8)  = __floats2half2_rn(c12, c13);
            *(__half2*)(zp + colb + 16) = __floats2half2_rn(c22, c23);
            *(__half2*)(zp + colb + 24) = __floats2half2_rn(c32, c33);
        }
    }
#undef LOAD_A
#undef MMA_STEP
}

// ---------------------------------------------------------------------------
// Kernel 2: per-edge dot on fp16 tables (unchanged from the 139.3us pass).
// ---------------------------------------------------------------------------
__device__ __forceinline__ float dot8h(float4 a, float4 v) {
    const __half2* ah = (const __half2*)&a;
    const __half2* vh = (const __half2*)&v;
    __half2 p0 = __hmul2(ah[0], vh[0]);
    __half2 p1 = __hmul2(ah[1], vh[1]);
    __half2 p2 = __hmul2(ah[2], vh[2]);
    __half2 p3 = __hmul2(ah[3], vh[3]);
    float2 q0 = __half22float2(p0);
    float2 q1 = __half22float2(p1);
    float2 q2 = __half22float2(p2);
    float2 q3 = __half22float2(p3);
    return ((q0.x + q0.y) + (q1.x + q1.y)) + ((q2.x + q2.y) + (q3.x + q3.y));
}

#define EDGES_PER_WARP 8

__global__ void __launch_bounds__(256) edge_dot_kernel(
    const void* __restrict__ eli_raw,
    const float* __restrict__ bias,
    float* __restrict__ out,
    int E, unsigned int Nm1) {
    const int gwarp = (blockIdx.x * blockDim.x + threadIdx.x) >> 5;
    const int lane  = threadIdx.x & 31;
    const int half  = lane >> 4;
    const int sub   = lane & 15;

    const int e0 = gwarp * EDGES_PER_WARP;
    if (e0 >= E) return;

    const int is64 = g_idx_is64;

    // coalesced index fetch: lanes 0-7 src[e0..e0+7], lanes 8-15 tgt[e0..e0+7]
    unsigned int myIdx = 0;
    if (lane < 16) {
        int e = min(e0 + (lane & 7), E - 1);
        if (is64) {
            const long long* p = (const long long*)eli_raw;
            myIdx = (unsigned int)__ldg(&p[(lane < 8 ? 0ll : (long long)E) + e]);
        } else {
            const int* p = (const int*)eli_raw;
            myIdx = (unsigned int)__ldg(&p[(lane < 8 ? 0 : E) + e]);
        }
        myIdx = min(myIdx, Nm1);
    }

    unsigned int sIdx[4], tIdx[4];
#pragma unroll
    for (int j = 0; j < 4; j++) {
        sIdx[j] = __shfl_sync(0xFFFFFFFFu, myIdx, 2 * j + half);
        tIdx[j] = __shfl_sync(0xFFFFFFFFu, myIdx, 8 + 2 * j + half);
    }

    float4 a[4], v[4];
#pragma unroll
    for (int j = 0; j < 4; j++) {
        a[j] = __ldg((const float4*)(g_xs_h + ((size_t)sIdx[j] << 7) + (sub << 3)));
        v[j] = __ldg((const float4*)(g_z_h  + ((size_t)tIdx[j] << 7) + (sub << 3)));
    }

    const float bv = __ldg(bias);

#pragma unroll
    for (int j = 0; j < 4; j++) {
        float acc = dot8h(a[j], v[j]);
#pragma unroll
        for (int o = 8; o > 0; o >>= 1)
            acc += __shfl_down_sync(0xFFFFFFFFu, acc, o, 16);
        if (sub == 0) {
            int e = min(e0 + 2 * j + half, E - 1);  // tail duplicates identical
            __stcs(&out[e], acc + bv);
        }
    }
}

// ---------------------------------------------------------------------------
extern "C" void kernel_launch(void* const* d_in, const int* in_sizes, int n_in,
                              void* d_out, int out_size) {
    const float* x_source = nullptr;
    const float* x_target = nullptr;
    const void*  eli      = nullptr;
    const float* W        = nullptr;
    const float* bias     = nullptr;
    int N = 0;
    const int E = out_size;

    for (int i = 0; i < n_in; i++) {
        int sz = in_sizes[i];
        if (sz == NDIM * NDIM)      W    = (const float*)d_in[i];
        else if (sz == 1)           bias = (const float*)d_in[i];
        else if (sz == 2 * E)       eli  = d_in[i];
        else {
            if (!x_source) { x_source = (const float*)d_in[i]; N = sz / NDIM; }
            else           { x_target = (const float*)d_in[i]; }
        }
    }

    float* out = (float*)d_out;

    int nwords = 2 * E; if (nwords > 4096) nwords = 4096;
    int n_elem4 = (N * NDIM) / 4;

    // 1) fused: GEMM blocks + convert blocks (+ idx-dtype detect)
    const int n_gemm = (N + 127) / 128;          // 782
    const int n_conv = n_gemm;                   // 16 float4 per thread
    const int dyn_smem = 2 * NDIM * APAD * (int)sizeof(__half);
    static int attr_set = 0;
    if (!attr_set) {
        cudaFuncSetAttribute(gemm_conv_kernel,
                             cudaFuncAttributeMaxDynamicSharedMemorySize, dyn_smem);
        attr_set = 1;
    }
    gemm_conv_kernel<<<n_gemm + n_conv, 256, dyn_smem>>>(
        x_target, W, x_source, n_elem4,
        (const int*)eli, nwords, N, n_gemm);

    // 2) per-edge gather + dot
    int warps_needed = (E + EDGES_PER_WARP - 1) / EDGES_PER_WARP;
    int nblocks = (warps_needed + 7) / 8;
    edge_dot_kernel<<<nblocks, 256>>>(eli, bias, out, E, (unsigned int)(N - 1));
}

// round 17
// speedup vs baseline: 1.0177x; 1.0177x over previous
#include <cuda_runtime.h>
#include <cuda_fp16.h>
#include <cstdint>

#define NDIM 128
#define MAX_NODES 100000
#define APAD 136   // smem row stride in halves (128 + 8): conflict-free fragments

// Scratch: fp16 z table, fp16 x_source copy, dtype flag.
__device__ __half g_z_h[MAX_NODES * NDIM];    // 25.6 MB
__device__ __half g_xs_h[MAX_NODES * NDIM];   // 25.6 MB
__device__ int    g_idx_is64;

// ---------------------------------------------------------------------------
// Kernel 1: convert x_source -> fp16 (vectorized x4)
//  + block 0: index-dtype detection (int64 values < 2^31 -> odd words all 0)
// ---------------------------------------------------------------------------
__global__ void __launch_bounds__(256) convert_xs_kernel(const float* __restrict__ xs,
                                                         int n_elem4,
                                                         const int* __restrict__ eli_words,
                                                         int nwords) {
    if (blockIdx.x == 0) {
        __shared__ int s_any_nonzero;
        if (threadIdx.x == 0) s_any_nonzero = 0;
        __syncthreads();
        for (int i = 1 + 2 * threadIdx.x; i < nwords; i += 2 * blockDim.x) {
            if (eli_words[i] != 0) { s_any_nonzero = 1; break; }
        }
        __syncthreads();
        if (threadIdx.x == 0) g_idx_is64 = (s_any_nonzero == 0) ? 1 : 0;
    }

    int i = blockIdx.x * blockDim.x + threadIdx.x;
    if (i >= n_elem4) return;
    float4 v = *(const float4*)(xs + (size_t)i * 4);
    *(__half2*)(g_xs_h + (size_t)i * 4)     = __floats2half2_rn(v.x, v.y);
    *(__half2*)(g_xs_h + (size_t)i * 4 + 2) = __floats2half2_rn(v.z, v.w);
}

// ---------------------------------------------------------------------------
// Kernel 2: tensor-core GEMM  z[m][d] = sum_f xt[m][f] * W[d][f]
// mma.sync.m16n8k16.row.col.f32.f16.f16.f32
// A tile STAGED in shared via bulk coalesced float4 loads (MLP 16).
// 16 NAMED SCALAR accumulators (register arrays => lmem => 128MiB violation).
// Dynamic smem: A[128][136] + W[128][136] fp16 = 68 KB.
// Block: 256 thr = 8 warps x 16 rows = 128 rows/block.
// ---------------------------------------------------------------------------
__global__ void __launch_bounds__(256) gemm_mma_kernel(const float* __restrict__ xt,
                                                       const float* __restrict__ W,
                                                       int n_rows) {
    extern __shared__ __half smem[];
    __half* A_sh = smem;                 // [128][APAD]
    __half* W_sh = smem + NDIM * APAD;   // [128][APAD]

    const int tid = threadIdx.x;
    const int block_base = blockIdx.x * 128;

    // --- stage W (fp32 -> fp16) ---
    for (int i = tid; i < NDIM * NDIM; i += 256) {
        int r = i >> 7;
        int c = i & (NDIM - 1);
        W_sh[r * APAD + c] = __float2half_rn(W[i]);
    }

    // --- stage A tile: 128 rows x 32 float4 = 4096 chunks, 16 per thread ---
#pragma unroll 4
    for (int i = tid; i < 128 * 32; i += 256) {
        int r  = i >> 5;          // local row 0..127
        int c4 = i & 31;          // float4 index 0..31
        int grow = block_base + r;
        if (grow >= n_rows) grow = n_rows - 1;   // clamp (stores guarded later)
        float4 v = *(const float4*)(xt + (size_t)grow * NDIM + c4 * 4);
        __half2 h0 = __floats2half2_rn(v.x, v.y);
        __half2 h1 = __floats2half2_rn(v.z, v.w);
        __half* p = A_sh + r * APAD + c4 * 4;
        *(__half2*)(p)     = h0;
        *(__half2*)(p + 2) = h1;
    }
    __syncthreads();

    const int warp = tid >> 5;
    const int lane = tid & 31;
    const int g = lane >> 2;        // 0..7
    const int t = lane & 3;         // 0..3
    const int row_base = block_base + warp * 16;
    if (row_base >= n_rows) return;

    const __half* Arow0 = A_sh + (warp * 16 + g)     * APAD + 2 * t;
    const __half* Arow1 = A_sh + (warp * 16 + g + 8) * APAD + 2 * t;
    const int row0 = row_base + g;
    const int row1 = row_base + g + 8;

#define LOAD_A(k0, a0, a1, a2, a3)                                   \
    unsigned int a0, a1, a2, a3;                                      \
    {                                                                 \
        a0 = *(const unsigned int*)(Arow0 + (k0));                    \
        a1 = *(const unsigned int*)(Arow1 + (k0));                    \
        a2 = *(const unsigned int*)(Arow0 + (k0) + 8);                \
        a3 = *(const unsigned int*)(Arow1 + (k0) + 8);                \
    }

#define MMA_STEP(k0, A0r, A1r, A2r, A3r, C0, C1, C2, C3, NROW)                    \
    {                                                                             \
        unsigned int b0 = *(const unsigned int*)(W_sh + ((NROW) + g) * APAD + (k0) + 2 * t);     \
        unsigned int b1 = *(const unsigned int*)(W_sh + ((NROW) + g) * APAD + (k0) + 2 * t + 8); \
        asm volatile(                                                             \
            "mma.sync.aligned.m16n8k16.row.col.f32.f16.f16.f32 "                  \
            "{%0,%1,%2,%3}, {%4,%5,%6,%7}, {%8,%9}, {%0,%1,%2,%3};"               \
            : "+f"(C0), "+f"(C1), "+f"(C2), "+f"(C3)                              \
            : "r"(A0r), "r"(A1r), "r"(A2r), "r"(A3r), "r"(b0), "r"(b1));          \
    }

#pragma unroll 1
    for (int ntg = 0; ntg < 4; ntg++) {
        const int n0 = ntg * 32;
        float c00 = 0.f, c01 = 0.f, c02 = 0.f, c03 = 0.f;
        float c10 = 0.f, c11 = 0.f, c12 = 0.f, c13 = 0.f;
        float c20 = 0.f, c21 = 0.f, c22 = 0.f, c23 = 0.f;
        float c30 = 0.f, c31 = 0.f, c32 = 0.f, c33 = 0.f;

#pragma unroll 1
        for (int k0 = 0; k0 < NDIM; k0 += 32) {
            LOAD_A(k0,      p0, p1, p2, p3)
            LOAD_A(k0 + 16, q0, q1, q2, q3)

            MMA_STEP(k0, p0, p1, p2, p3, c00, c01, c02, c03, n0)
            MMA_STEP(k0, p0, p1, p2, p3, c10, c11, c12, c13, n0 + 8)
            MMA_STEP(k0, p0, p1, p2, p3, c20, c21, c22, c23, n0 + 16)
            MMA_STEP(k0, p0, p1, p2, p3, c30, c31, c32, c33, n0 + 24)

            MMA_STEP(k0 + 16, q0, q1, q2, q3, c00, c01, c02, c03, n0)
            MMA_STEP(k0 + 16, q0, q1, q2, q3, c10, c11, c12, c13, n0 + 8)
            MMA_STEP(k0 + 16, q0, q1, q2, q3, c20, c21, c22, c23, n0 + 16)
            MMA_STEP(k0 + 16, q0, q1, q2, q3, c30, c31, c32, c33, n0 + 24)
        }

        const int colb = n0 + 2 * t;
        if (row0 < n_rows) {
            __half* zp = g_z_h + (size_t)row0 * NDIM;
            *(__half2*)(zp + colb)      = __floats2half2_rn(c00, c01);
            *(__half2*)(zp + colb + 8)  = __floats2half2_rn(c10, c11);
            *(__half2*)(zp + colb + 16) = __floats2half2_rn(c20, c21);
            *(__half2*)(zp + colb + 24) = __floats2half2_rn(c30, c31);
        }
        if (row1 < n_rows) {
            __half* zp = g_z_h + (size_t)row1 * NDIM;
            *(__half2*)(zp + colb)      = __floats2half2_rn(c02, c03);
            *(__half2*)(zp + colb + 8)  = __floats2half2_rn(c12, c13);
            *(__half2*)(zp + colb + 16) = __floats2half2_rn(c22, c23);
            *(__half2*)(zp + colb + 24) = __floats2half2_rn(c32, c33);
        }
    }
#undef LOAD_A
#undef MMA_STEP
}

// ---------------------------------------------------------------------------
// Kernel 3: per-edge dot on fp16 tables (R15 version, part of best config).
// ---------------------------------------------------------------------------
__device__ __forceinline__ float dot8h(float4 a, float4 v) {
    const __half2* ah = (const __half2*)&a;
    const __half2* vh = (const __half2*)&v;
    __half2 p0 = __hmul2(ah[0], vh[0]);
    __half2 p1 = __hmul2(ah[1], vh[1]);
    __half2 p2 = __hmul2(ah[2], vh[2]);
    __half2 p3 = __hmul2(ah[3], vh[3]);
    float2 q0 = __half22float2(p0);
    float2 q1 = __half22float2(p1);
    float2 q2 = __half22float2(p2);
    float2 q3 = __half22float2(p3);
    return ((q0.x + q0.y) + (q1.x + q1.y)) + ((q2.x + q2.y) + (q3.x + q3.y));
}

#define EDGES_PER_WARP 8

__global__ void __launch_bounds__(256) edge_dot_kernel(
    const void* __restrict__ eli_raw,
    const float* __restrict__ bias,
    float* __restrict__ out,
    int E, unsigned int Nm1) {
    const int gwarp = (blockIdx.x * blockDim.x + threadIdx.x) >> 5;
    const int lane  = threadIdx.x & 31;
    const int half  = lane >> 4;
    const int sub   = lane & 15;

    const int e0 = gwarp * EDGES_PER_WARP;
    if (e0 >= E) return;

    const int is64 = g_idx_is64;

    // coalesced index fetch: lanes 0-7 src[e0..e0+7], lanes 8-15 tgt[e0..e0+7]
    unsigned int myIdx = 0;
    if (lane < 16) {
        int e = min(e0 + (lane & 7), E - 1);
        if (is64) {
            const long long* p = (const long long*)eli_raw;
            myIdx = (unsigned int)__ldg(&p[(lane < 8 ? 0ll : (long long)E) + e]);
        } else {
            const int* p = (const int*)eli_raw;
            myIdx = (unsigned int)__ldg(&p[(lane < 8 ? 0 : E) + e]);
        }
        myIdx = min(myIdx, Nm1);
    }

    unsigned int sIdx[4], tIdx[4];
#pragma unroll
    for (int j = 0; j < 4; j++) {
        sIdx[j] = __shfl_sync(0xFFFFFFFFu, myIdx, 2 * j + half);
        tIdx[j] = __shfl_sync(0xFFFFFFFFu, myIdx, 8 + 2 * j + half);
    }

    float4 a[4], v[4];
#pragma unroll
    for (int j = 0; j < 4; j++) {
        a[j] = __ldg((const float4*)(g_xs_h + ((size_t)sIdx[j] << 7) + (sub << 3)));
        v[j] = __ldg((const float4*)(g_z_h  + ((size_t)tIdx[j] << 7) + (sub << 3)));
    }

    const float bv = __ldg(bias);

#pragma unroll
    for (int j = 0; j < 4; j++) {
        float acc = dot8h(a[j], v[j]);
#pragma unroll
        for (int o = 8; o > 0; o >>= 1)
            acc += __shfl_down_sync(0xFFFFFFFFu, acc, o, 16);
        if (sub == 0) {
            int e = min(e0 + 2 * j + half, E - 1);  // tail duplicates identical
            __stcs(&out[e], acc + bv);
        }
    }
}

// ---------------------------------------------------------------------------
// Launch topology: graph fork-join.
//   main stream: gemm ------\
//                             join -> edge
//   side stream: convert ---/
// Stream/events created lazily on the first (non-captured) correctness call;
// capture calls only replay launches + event record/wait (graph-legal).
// ---------------------------------------------------------------------------
extern "C" void kernel_launch(void* const* d_in, const int* in_sizes, int n_in,
                              void* d_out, int out_size) {
    const float* x_source = nullptr;
    const float* x_target = nullptr;
    const void*  eli      = nullptr;
    const float* W        = nullptr;
    const float* bias     = nullptr;
    int N = 0;
    const int E = out_size;

    for (int i = 0; i < n_in; i++) {
        int sz = in_sizes[i];
        if (sz == NDIM * NDIM)      W    = (const float*)d_in[i];
        else if (sz == 1)           bias = (const float*)d_in[i];
        else if (sz == 2 * E)       eli  = d_in[i];
        else {
            if (!x_source) { x_source = (const float*)d_in[i]; N = sz / NDIM; }
            else           { x_target = (const float*)d_in[i]; }
        }
    }

    float* out = (float*)d_out;

    int nwords = 2 * E; if (nwords > 4096) nwords = 4096;
    int n_elem4 = (N * NDIM) / 4;
    const int dyn_smem = 2 * NDIM * APAD * (int)sizeof(__half);

    static cudaStream_t s_side = nullptr;
    static cudaEvent_t  s_fork = nullptr, s_join = nullptr;
    if (!s_side) {
        cudaStreamCreateWithFlags(&s_side, cudaStreamNonBlocking);
        cudaEventCreateWithFlags(&s_fork, cudaEventDisableTiming);
        cudaEventCreateWithFlags(&s_join, cudaEventDisableTiming);
        cudaFuncSetAttribute(gemm_mma_kernel,
                             cudaFuncAttributeMaxDynamicSharedMemorySize, dyn_smem);
    }

    // fork: side stream inherits main-stream state
    cudaEventRecord(s_fork, 0);
    cudaStreamWaitEvent(s_side, s_fork, 0);

    // side branch: convert x_source -> fp16 (+ idx dtype detect)
    convert_xs_kernel<<<(n_elem4 + 255) / 256, 256, 0, s_side>>>(
        x_source, n_elem4, (const int*)eli, nwords);

    // main branch: z = xt @ W^T via tensor cores
    gemm_mma_kernel<<<(N + 127) / 128, 256, dyn_smem>>>(x_target, W, N);

    // join: edge waits on both branches
    cudaEventRecord(s_join, s_side);
    cudaStreamWaitEvent(0, s_join, 0);

    int warps_needed = (E + EDGES_PER_WARP - 1) / EDGES_PER_WARP;
    int nblocks = (warps_needed + 7) / 8;
    edge_dot_kernel<<<nblocks, 256>>>(eli, bias, out, E, (unsigned int)(N - 1));
}